// round 17
// baseline (speedup 1.0000x reference)
#include <cuda_runtime.h>
#include <cuda_fp16.h>
#include <math.h>
#include <stdint.h>

#define NTOK 4096
#define CDIM 1024
#define HDIM 4096
#define NEXP 8
#define NSLOT (NTOK * 2)

// GEMM geometry: block tile 128(M) x 128(N) x 64(K) fp16.
// 288 threads = 8 compute warps (2m x 4n, warp 64x32) + 1 producer warp (cp.async only).
// 5-stage smem pipeline, named-barrier producer/consumer handoff.
#define NSTAGE 5
#define STAGE_BYTES 32768            // A 16KB + B 16KB
#define SMEM_BYTES  (NSTAGE * STAGE_BYTES)

// ---------------- static device scratch ----------------
__device__ int g_offsets[NEXP + 1];
__device__ __align__(16) int g_rtok[NSLOT];
__device__ int g_e1[NTOK], g_e2[NTOK];
__device__ int g_s1[NTOK], g_s2[NTOK];
__device__ float g_w1[NTOK], g_w2[NTOK];
__device__ __align__(256) __half g_x16[(size_t)NTOK * CDIM];          // 8 MiB
__device__ __align__(256) __half g_w1h[(size_t)NEXP * CDIM * HDIM];   // 64 MiB
__device__ __align__(256) __half g_w2h[(size_t)NEXP * HDIM * CDIM];   // 64 MiB
__device__ __align__(256) __half g_h[(size_t)NSLOT * HDIM];           // 64 MiB
__device__ __align__(256) float  g_y[(size_t)NSLOT * CDIM];           // 32 MiB

#define NX4  (NTOK * CDIM / 4)
#define NW4  (NEXP * CDIM * HDIM / 4)

// ---------------- helpers ----------------
__device__ __forceinline__ uint32_t smem_u32(const void* p) {
    uint32_t a;
    asm("{ .reg .u64 t; cvta.to.shared.u64 t, %1; cvt.u32.u64 %0, t; }" : "=r"(a) : "l"(p));
    return a;
}
#define SWZ(o)    ((o) ^ ((((uint32_t)(o)) >> 3) & 0x70u))   // 128B rows
#define SWZ256(o) ((o) ^ ((((uint32_t)(o)) >> 4) & 0x70u))   // 256B rows

#define BARS(id) asm volatile("bar.sync %0, 288;"   :: "r"(id) : "memory")
#define BARA(id) asm volatile("bar.arrive %0, 288;" :: "r"(id) : "memory")

__device__ __forceinline__ void cp16(uint32_t dst, const void* src) {
    asm volatile("cp.async.cg.shared.global [%0], [%1], 16;" :: "r"(dst), "l"(src) : "memory");
}
__device__ __forceinline__ void ldsm4(uint32_t& r0, uint32_t& r1, uint32_t& r2, uint32_t& r3, uint32_t a) {
    asm volatile("ldmatrix.sync.aligned.m8n8.x4.shared.b16 {%0,%1,%2,%3}, [%4];"
                 : "=r"(r0), "=r"(r1), "=r"(r2), "=r"(r3) : "r"(a));
}
__device__ __forceinline__ void ldsm4t(uint32_t& r0, uint32_t& r1, uint32_t& r2, uint32_t& r3, uint32_t a) {
    asm volatile("ldmatrix.sync.aligned.m8n8.x4.trans.shared.b16 {%0,%1,%2,%3}, [%4];"
                 : "=r"(r0), "=r"(r1), "=r"(r2), "=r"(r3) : "r"(a));
}
__device__ __forceinline__ void mma_f16(float* c, uint32_t a0, uint32_t a1, uint32_t a2, uint32_t a3,
                                        uint32_t b0, uint32_t b1) {
    asm volatile(
        "mma.sync.aligned.m16n8k16.row.col.f32.f16.f16.f32 "
        "{%0,%1,%2,%3}, {%4,%5,%6,%7}, {%8,%9}, {%0,%1,%2,%3};"
        : "+f"(c[0]), "+f"(c[1]), "+f"(c[2]), "+f"(c[3])
        : "r"(a0), "r"(a1), "r"(a2), "r"(a3), "r"(b0), "r"(b1));
}
__device__ __forceinline__ uint32_t h2u(__half2 h) { return *(uint32_t*)&h; }
__device__ __forceinline__ float gelu_exact(float v) {
    return 0.5f * v * (1.0f + erff(v * 0.70710678118654752f));
}
__device__ __forceinline__ void cvt_slice(const float4* __restrict__ src, uint2* __restrict__ dst,
                                          int start, int count, int tid, int nthr) {
    for (int i = start + tid; i < start + count; i += nthr) {
        float4 v = src[i];
        uint2 o;
        o.x = h2u(__floats2half2_rn(v.x, v.y));
        o.y = h2u(__floats2half2_rn(v.z, v.w));
        dst[i] = o;
    }
}

// ---------------- gate + x/W1 cvt (512 blocks x 256 thr) — proven ----------------
__global__ void k_gate(const float* __restrict__ x, const float* __restrict__ Wg,
                       const float* __restrict__ bg, const float* __restrict__ W1) {
    int warp = (blockIdx.x * blockDim.x + threadIdx.x) >> 5;
    int lane = threadIdx.x & 31;
    if (warp < NTOK) {
        const float* xr = x + (size_t)warp * CDIM;
        float acc[NEXP];
#pragma unroll
        for (int e = 0; e < NEXP; e++) acc[e] = 0.f;
        for (int k = lane; k < CDIM; k += 32) {
            float xv = xr[k];
            const float* wr = Wg + k * NEXP;
#pragma unroll
            for (int e = 0; e < NEXP; e++) acc[e] = fmaf(xv, wr[e], acc[e]);
        }
#pragma unroll
        for (int off = 16; off; off >>= 1)
#pragma unroll
            for (int e = 0; e < NEXP; e++)
                acc[e] += __shfl_xor_sync(0xffffffffu, acc[e], off);
        if (lane == 0) {
#pragma unroll
            for (int e = 0; e < NEXP; e++) acc[e] += bg[e];
            int b1i = 0; float b1v = acc[0];
#pragma unroll
            for (int e = 1; e < NEXP; e++) if (acc[e] > b1v) { b1v = acc[e]; b1i = e; }
            int b2i = -1; float b2v = -3.0e38f;
#pragma unroll
            for (int e = 0; e < NEXP; e++)
                if (e != b1i && acc[e] > b2v) { b2v = acc[e]; b2i = e; }
            float p2 = expf(b2v - b1v);
            float inv = 1.f / (1.f + p2);
            g_e1[warp] = b1i; g_e2[warp] = b2i;
            g_w1[warp] = inv; g_w2[warp] = p2 * inv;
        }
    }
    const int bid = blockIdx.x;                 // 512 blocks
    const int xper = NX4 / 512;
    const int wper = NW4 / 512;
    cvt_slice((const float4*)x,  (uint2*)g_x16, bid * xper, xper, threadIdx.x, 256);
    cvt_slice((const float4*)W1, (uint2*)g_w1h, bid * wper, wper, threadIdx.x, 256);
}

// ---------------- route: counts+prefix+scatter, single block ----------------
__global__ void k_route() {
    __shared__ int cnt[NEXP];
    __shared__ int base[NEXP];
    const int tid = threadIdx.x;                // 1024 threads
    if (tid < NEXP) cnt[tid] = 0;
    __syncthreads();
#pragma unroll
    for (int q = 0; q < 4; q++) {
        int t = tid + q * 1024;
        atomicAdd(&cnt[g_e1[t]], 1);
        atomicAdd(&cnt[g_e2[t]], 1);
    }
    __syncthreads();
    if (tid == 0) {
        int off = 0;
        for (int e = 0; e < NEXP; e++) {
            g_offsets[e] = off;
            base[e] = off;
            off += cnt[e];
        }
        g_offsets[NEXP] = off;
    }
    __syncthreads();
#pragma unroll
    for (int q = 0; q < 4; q++) {
        int t = tid + q * 1024;
        int s1 = atomicAdd(&base[g_e1[t]], 1);
        g_rtok[s1] = t; g_s1[t] = s1;
        int s2 = atomicAdd(&base[g_e2[t]], 1);
        g_rtok[s2] = t; g_s2[t] = s2;
    }
}

// ---------------- warp-specialized fp16 HMMA mainloop ----------------
// Consumers (tid<256): per chunk: READY-sync -> preload all B frags -> 16x(ldsm A + 4 MMA) -> FREE-arrive.
// Producer (warp 8): per chunk: FREE-sync (j>=NSTAGE) -> cp.async A+B -> commit -> wait_group 1 -> READY-arrive(j-1).
template <int NCH>
__device__ __forceinline__ void ws_loop(
    uint32_t sb, int tid,
    const __half* const (&pa)[4], const __half* pbsrc, int ldb,
    float (&acc)[4][4][4])
{
    if (tid < 256) {
        const int lane = tid & 31, wid = tid >> 5;
        const int wm = (wid >> 2) * 64, wn = (wid & 3) * 32;
        const int g = lane >> 3, r = lane & 7;
        for (int i = 0; i < NCH; i++) {
            const int s = i % NSTAGE;
            BARS(6 + s);
            uint32_t As = sb + (uint32_t)s * STAGE_BYTES;
            uint32_t Bb = As + 16384u;
            uint32_t bf[4][4][2];
#pragma unroll
            for (int ks = 0; ks < 4; ks++)
#pragma unroll
                for (int p = 0; p < 2; p++) {
                    uint32_t krow = (uint32_t)(ks * 16 + (g & 1) * 8 + r);
                    uint32_t nby  = (uint32_t)(wn + p * 16 + (g >> 1) * 8) * 2u;
                    ldsm4t(bf[ks][2 * p][0], bf[ks][2 * p][1],
                           bf[ks][2 * p + 1][0], bf[ks][2 * p + 1][1],
                           Bb + SWZ256(krow * 256u + nby));
                }
#pragma unroll
            for (int ks = 0; ks < 4; ks++)
#pragma unroll
                for (int ms = 0; ms < 4; ms++) {
                    uint32_t row  = (uint32_t)(wm + ms * 16 + (lane & 15));
                    uint32_t colb = (uint32_t)(ks * 32 + (lane >> 4) * 16);
                    uint32_t a0, a1, a2, a3;
                    ldsm4(a0, a1, a2, a3, As + SWZ(row * 128u + colb));
#pragma unroll
                    for (int ns = 0; ns < 4; ns++)
                        mma_f16(acc[ms][ns], a0, a1, a2, a3, bf[ks][ns][0], bf[ks][ns][1]);
                }
            BARA(1 + s);
        }
    } else {
        const int pl = tid - 256;              // 0..31
        for (int j = 0; j < NCH; j++) {
            const int s = j % NSTAGE;
            if (j >= NSTAGE) BARS(1 + s);
            uint32_t As = sb + (uint32_t)s * STAGE_BYTES;
            uint32_t Bb = As + 16384u;
#pragma unroll
            for (int q = 0; q < 4; q++) {
                int rr = pl * 4 + q;           // tile-local row 0..127
                uint32_t abase = As + (uint32_t)rr * 128u;
                const __half* src = pa[q] + (size_t)j * 64;
#pragma unroll
                for (int c = 0; c < 8; c++)
                    cp16(abase + (uint32_t)((c ^ (rr & 7)) * 16), src + c * 8);
            }
#pragma unroll
            for (int q = 0; q < 2; q++) {
                int kk = pl * 2 + q;           // k-row 0..63
                uint32_t bbase = Bb + (uint32_t)kk * 256u;
                const __half* src = pbsrc + ((size_t)j * 64 + kk) * ldb;
#pragma unroll
                for (int c = 0; c < 16; c++)
                    cp16(bbase + (uint32_t)((c ^ (kk & 7)) * 16), src + c * 8);
            }
            asm volatile("cp.async.commit_group;" ::: "memory");
            if (j >= 1) {
                asm volatile("cp.async.wait_group 1;" ::: "memory");
                BARA(6 + ((j - 1) % NSTAGE));
            }
        }
        asm volatile("cp.async.wait_group 0;" ::: "memory");
        BARA(6 + ((NCH - 1) % NSTAGE));
    }
}

// ---------------- GEMM1 + folded W2 conversion ----------------
__global__ __launch_bounds__(288, 1)
void k_gemm1(const float* __restrict__ b1, const float* __restrict__ W2) {
    // W2 cvt slice (all blocks) — overlaps gemm1 compute across the grid
    {
        const int nb  = 32 * 32 * NEXP;                       // 8192 blocks
        const int bid = blockIdx.x + 32 * (blockIdx.y + 32 * blockIdx.z);
        const int per = NW4 / nb;
        cvt_slice((const float4*)W2, (uint2*)g_w2h, bid * per, per, threadIdx.x, 288);
    }

    const int e  = blockIdx.z;
    const int off = g_offsets[e];
    const int ne  = g_offsets[e + 1] - off;
    const int m0  = blockIdx.y * 128;
    if (m0 >= ne) return;
    const int n0  = blockIdx.x * 128;

    extern __shared__ __align__(1024) char smem[];
    uint32_t sb = smem_u32(smem);
    const int tid = threadIdx.x;

    const __half* pa[4] = {nullptr, nullptr, nullptr, nullptr};
    if (tid >= 256) {
        const int pl = tid - 256;
#pragma unroll
        for (int q = 0; q < 4; q++) {
            int rr = m0 + pl * 4 + q;
            int tok = g_rtok[off + (rr < ne ? rr : 0)];
            pa[q] = g_x16 + (size_t)tok * CDIM;
        }
    }
    const __half* pbsrc = g_w1h + (size_t)e * CDIM * HDIM + n0;

    float acc[4][4][4];
#pragma unroll
    for (int a = 0; a < 4; a++)
#pragma unroll
        for (int b = 0; b < 4; b++)
#pragma unroll
            for (int c = 0; c < 4; c++) acc[a][b][c] = 0.f;

    ws_loop<CDIM / 64>(sb, tid, pa, pbsrc, HDIM, acc);

    if (tid < 256) {
        const int lane = tid & 31, wid = tid >> 5;
        const int grp = lane >> 2, tq = lane & 3;
        const int wm = (wid >> 2) * 64, wn = (wid & 3) * 32;
        const float* brow = b1 + (size_t)e * HDIM + n0 + wn;
#pragma unroll
        for (int ms = 0; ms < 4; ms++)
#pragma unroll
            for (int h = 0; h < 2; h++) {
                int rr = m0 + wm + ms * 16 + grp + h * 8;
                if (rr < ne) {
                    __half* hrow = g_h + (size_t)(off + rr) * HDIM + n0 + wn;
#pragma unroll
                    for (int ns = 0; ns < 4; ns++) {
                        int col = ns * 8 + 2 * tq;
                        __half2 o = __floats2half2_rn(
                            gelu_exact(acc[ms][ns][h * 2 + 0] + brow[col]),
                            gelu_exact(acc[ms][ns][h * 2 + 1] + brow[col + 1]));
                        *(__half2*)(hrow + col) = o;
                    }
                }
            }
    }
}

// ---------------- GEMM2: y = h_slots @ W2h[e] + b2[e] ----------------
__global__ __launch_bounds__(288, 1)
void k_gemm2(const float* __restrict__ b2) {
    const int e  = blockIdx.z;
    const int off = g_offsets[e];
    const int ne  = g_offsets[e + 1] - off;
    const int m0  = blockIdx.y * 128;
    if (m0 >= ne) return;
    const int n0  = blockIdx.x * 128;

    extern __shared__ __align__(1024) char smem[];
    uint32_t sb = smem_u32(smem);
    const int tid = threadIdx.x;

    const __half* pa[4] = {nullptr, nullptr, nullptr, nullptr};
    if (tid >= 256) {
        const int pl = tid - 256;
#pragma unroll
        for (int q = 0; q < 4; q++) {
            int rr = m0 + pl * 4 + q;
            if (rr >= ne) rr = ne - 1;
            pa[q] = g_h + (size_t)(off + rr) * HDIM;
        }
    }
    const __half* pbsrc = g_w2h + (size_t)e * HDIM * CDIM + n0;

    float acc[4][4][4];
#pragma unroll
    for (int a = 0; a < 4; a++)
#pragma unroll
        for (int b = 0; b < 4; b++)
#pragma unroll
            for (int c = 0; c < 4; c++) acc[a][b][c] = 0.f;

    ws_loop<HDIM / 64>(sb, tid, pa, pbsrc, CDIM, acc);

    if (tid < 256) {
        const int lane = tid & 31, wid = tid >> 5;
        const int grp = lane >> 2, tq = lane & 3;
        const int wm = (wid >> 2) * 64, wn = (wid & 3) * 32;
        const float* brow = b2 + (size_t)e * CDIM + n0 + wn;
#pragma unroll
        for (int ms = 0; ms < 4; ms++)
#pragma unroll
            for (int h = 0; h < 2; h++) {
                int rr = m0 + wm + ms * 16 + grp + h * 8;
                if (rr < ne) {
                    float* yrow = g_y + (size_t)(off + rr) * CDIM + n0 + wn;
#pragma unroll
                    for (int ns = 0; ns < 4; ns++) {
                        int col = ns * 8 + 2 * tq;
                        float2 o;
                        o.x = acc[ms][ns][h * 2 + 0] + brow[col];
                        o.y = acc[ms][ns][h * 2 + 1] + brow[col + 1];
                        *(float2*)(yrow + col) = o;
                    }
                }
            }
    }
}

// ---------------- combine: out[t] = w1*y[s1] + w2*y[s2] ----------------
__global__ void k_combine(float* __restrict__ out) {
    int t = blockIdx.x;
    int c = threadIdx.x * 4;
    float w1 = g_w1[t], w2 = g_w2[t];
    const float4 a = *(const float4*)(g_y + (size_t)g_s1[t] * CDIM + c);
    const float4 b = *(const float4*)(g_y + (size_t)g_s2[t] * CDIM + c);
    float4 o;
    o.x = w1 * a.x + w2 * b.x;
    o.y = w1 * a.y + w2 * b.y;
    o.z = w1 * a.z + w2 * b.z;
    o.w = w1 * a.w + w2 * b.w;
    *(float4*)(out + (size_t)t * CDIM + c) = o;
}

extern "C" void kernel_launch(void* const* d_in, const int* in_sizes, int n_in,
                              void* d_out, int out_size) {
    const float* x  = (const float*)d_in[0];
    const float* Wg = (const float*)d_in[1];
    const float* bg = (const float*)d_in[2];
    const float* W1 = (const float*)d_in[3];
    const float* b1 = (const float*)d_in[4];
    const float* W2 = (const float*)d_in[5];
    const float* b2 = (const float*)d_in[6];
    float* out = (float*)d_out;

    cudaFuncSetAttribute(k_gemm1, cudaFuncAttributeMaxDynamicSharedMemorySize, SMEM_BYTES);
    cudaFuncSetAttribute(k_gemm2, cudaFuncAttributeMaxDynamicSharedMemorySize, SMEM_BYTES);

    k_gate<<<512, 256>>>(x, Wg, bg, W1);   // gate + x/W1 cvt
    k_route<<<1, 1024>>>();                // counts + prefix + scatter

    dim3 grd1(HDIM / 128, 32, NEXP);       // 128-row M tiles; W2 cvt folded in
    k_gemm1<<<grd1, 288, SMEM_BYTES>>>(b1, W2);
    dim3 grd2(CDIM / 128, 32, NEXP);
    k_gemm2<<<grd2, 288, SMEM_BYTES>>>(b2);
    k_combine<<<NTOK, 256>>>(out);
}